// round 12
// baseline (speedup 1.0000x reference)
#include <cuda_runtime.h>
#include <cuda_bf16.h>
#include <math.h>

// ---------------------------------------------------------------------------
// Problem constants
// ---------------------------------------------------------------------------
#define B_     4
#define T_     1024
#define DIM_   2048
#define H_     16
#define HKV_   4
#define DH_    128
#define HID_   8192
#define M_TOK  (B_ * T_)          // 4096 rows
typedef __nv_bfloat16 bf16;

// ---------------------------------------------------------------------------
// Static device scratch (no dynamic allocation allowed)
// ---------------------------------------------------------------------------
__device__ float g_q [M_TOK * DIM_];              // Q fp32 (pre-rope)
__device__ float g_k [M_TOK * HKV_ * DH_];        // K fp32 (pre-rope)
__device__ float g_v [M_TOK * HKV_ * DH_];        // V fp32
__device__ float g_s [(size_t)B_ * H_ * T_ * T_]; // scores fp32

__device__ bf16 g_ah [M_TOK * DIM_];              // normed act hi/lo
__device__ bf16 g_al [M_TOK * DIM_];
__device__ bf16 g_qh [M_TOK * DIM_];              // roped Q hi/lo
__device__ bf16 g_ql [M_TOK * DIM_];
__device__ bf16 g_kh [M_TOK * HKV_ * DH_];        // roped K hi/lo
__device__ bf16 g_kl [M_TOK * HKV_ * DH_];
__device__ bf16 g_vth[M_TOK * HKV_ * DH_];        // V^T hi/lo  [b,kv][128][1024]
__device__ bf16 g_vtl[M_TOK * HKV_ * DH_];
__device__ bf16 g_ph [(size_t)B_ * H_ * T_ * T_]; // probs hi/lo
__device__ bf16 g_pl [(size_t)B_ * H_ * T_ * T_];
__device__ bf16 g_yh [M_TOK * DIM_];              // attn out hi/lo
__device__ bf16 g_yl [M_TOK * DIM_];
__device__ bf16 g_hh [M_TOK * HID_];              // silu(h1)*h2 hi/lo
__device__ bf16 g_hl [M_TOK * HID_];

// transposed bf16 weights [N,K]
__device__ bf16 g_wqkv_h[(DIM_ + 2*HKV_*DH_) * DIM_];
__device__ bf16 g_wqkv_l[(DIM_ + 2*HKV_*DH_) * DIM_];
__device__ bf16 g_wo_h [DIM_ * DIM_];
__device__ bf16 g_wo_l [DIM_ * DIM_];
__device__ bf16 g_w12_h[(size_t)2 * HID_ * DIM_];
__device__ bf16 g_w12_l[(size_t)2 * HID_ * DIM_];
__device__ bf16 g_w3_h [(size_t)DIM_ * HID_];
__device__ bf16 g_w3_l [(size_t)DIM_ * HID_];

// ---------------------------------------------------------------------------
// Small helpers
// ---------------------------------------------------------------------------
__device__ __forceinline__ unsigned smem_u32(const void* p) {
    return (unsigned)__cvta_generic_to_shared(p);
}
__device__ __forceinline__ void cp16(unsigned dst, const void* src) {
    asm volatile("cp.async.cg.shared.global [%0], [%1], 16;" :: "r"(dst), "l"(src));
}
__device__ __forceinline__ void cp_commit() { asm volatile("cp.async.commit_group;"); }
__device__ __forceinline__ void cp_wait0()  { asm volatile("cp.async.wait_group 0;"); }

// mma.sync m16n8k16 bf16 (plain compute_103-safe)
__device__ __forceinline__ void mma16816(float* c, const unsigned* a, const unsigned* b) {
    asm volatile(
        "mma.sync.aligned.m16n8k16.row.col.f32.bf16.bf16.f32 "
        "{%0,%1,%2,%3}, {%4,%5,%6,%7}, {%8,%9}, {%0,%1,%2,%3};"
        : "+f"(c[0]), "+f"(c[1]), "+f"(c[2]), "+f"(c[3])
        : "r"(a[0]), "r"(a[1]), "r"(a[2]), "r"(a[3]), "r"(b[0]), "r"(b[1]));
}
__device__ __forceinline__ void ldsm4(unsigned* r, unsigned addr) {
    asm volatile("ldmatrix.sync.aligned.m8n8.x4.shared.b16 {%0,%1,%2,%3}, [%4];"
                 : "=r"(r[0]), "=r"(r[1]), "=r"(r[2]), "=r"(r[3]) : "r"(addr));
}

__device__ __forceinline__ void split_bf16(float v, bf16& hi, bf16& lo) {
    hi = __float2bfloat16(v);
    lo = __float2bfloat16(v - __bfloat162float(hi));
}

// ---------------------------------------------------------------------------
// Weight convert + transpose: src [Kd, Nd] fp32 -> dst_hi/lo [Nd, Kd] bf16
// ---------------------------------------------------------------------------
__global__ void __launch_bounds__(256) wsplit_t(
    const float* __restrict__ src, bf16* __restrict__ dh, bf16* __restrict__ dl,
    int Kd, int Nd, int row_off)
{
    __shared__ float tile[32][33];
    int tx = threadIdx.x, ty = threadIdx.y;          // (32, 8)
    int bx = blockIdx.x * 32;                        // N dim
    int by = blockIdx.y * 32;                        // K dim
    #pragma unroll
    for (int j = 0; j < 4; j++)
        tile[ty + 8*j][tx] = src[(size_t)(by + ty + 8*j) * Nd + bx + tx];
    __syncthreads();
    #pragma unroll
    for (int j = 0; j < 4; j++) {
        float v = tile[tx][ty + 8*j];
        bf16 hi, lo; split_bf16(v, hi, lo);
        size_t o = (size_t)(row_off + bx + ty + 8*j) * Kd + by + tx;
        dh[o] = hi; dl[o] = lo;
    }
}

// ---------------------------------------------------------------------------
// V transpose + split: v fp32 [4096, 512] -> vt hi/lo [(b*4+kv)*128 + d][1024]
// grid (4, 32, 16) block (32, 8)
// ---------------------------------------------------------------------------
__global__ void __launch_bounds__(256) vsplit_t(
    const float* __restrict__ v, bf16* __restrict__ dh, bf16* __restrict__ dl)
{
    __shared__ float tile[32][33];
    int tx = threadIdx.x, ty = threadIdx.y;
    int z = blockIdx.z;                 // b*4 + kv
    int b = z >> 2, kv = z & 3;
    int sx = blockIdx.x * 32;           // d
    int sy = blockIdx.y * 32;           // s
    #pragma unroll
    for (int j = 0; j < 4; j++)
        tile[ty + 8*j][tx] =
            v[(size_t)(b*T_ + sy + ty + 8*j) * (HKV_*DH_) + kv*DH_ + sx + tx];
    __syncthreads();
    #pragma unroll
    for (int j = 0; j < 4; j++) {
        float val = tile[tx][ty + 8*j];
        bf16 hi, lo; split_bf16(val, hi, lo);
        size_t o = ((size_t)z*DH_ + sx + ty + 8*j) * T_ + sy + tx;
        dh[o] = hi; dl[o] = lo;
    }
}

// ---------------------------------------------------------------------------
// RMSNorm + bf16 hi/lo split: one block per row of 2048
// ---------------------------------------------------------------------------
__global__ void __launch_bounds__(256) rmsnorm_split(
    const float* __restrict__ x, const float* __restrict__ w,
    bf16* __restrict__ oh, bf16* __restrict__ ol)
{
    int row = blockIdx.x;
    const float4* xr = (const float4*)(x + (size_t)row * DIM_);
    const float4* wr = (const float4*)w;
    int tid = threadIdx.x;

    float4 v0 = xr[tid];
    float4 v1 = xr[tid + 256];
    float ss = v0.x*v0.x + v0.y*v0.y + v0.z*v0.z + v0.w*v0.w
             + v1.x*v1.x + v1.y*v1.y + v1.z*v1.z + v1.w*v1.w;

    #pragma unroll
    for (int o = 16; o > 0; o >>= 1) ss += __shfl_xor_sync(0xFFFFFFFFu, ss, o);
    __shared__ float red[8];
    if ((tid & 31) == 0) red[tid >> 5] = ss;
    __syncthreads();
    if (tid < 32) {
        float t = (tid < 8) ? red[tid] : 0.0f;
        #pragma unroll
        for (int o = 4; o > 0; o >>= 1) t += __shfl_xor_sync(0xFFFFFFFFu, t, o);
        if (tid == 0) red[0] = t;
    }
    __syncthreads();
    float scale = rsqrtf(red[0] * (1.0f / DIM_) + 1e-5f);

    float4 w0 = wr[tid];
    float4 w1 = wr[tid + 256];
    float vals[8] = { v0.x*scale*w0.x, v0.y*scale*w0.y, v0.z*scale*w0.z, v0.w*scale*w0.w,
                      v1.x*scale*w1.x, v1.y*scale*w1.y, v1.z*scale*w1.z, v1.w*scale*w1.w };
    size_t base = (size_t)row * DIM_;
    #pragma unroll
    for (int j = 0; j < 8; j++) {
        int col = (j < 4) ? (tid*4 + j) : (1024 + tid*4 + j - 4);
        bf16 hi, lo; split_bf16(vals[j], hi, lo);
        oh[base + col] = hi; ol[base + col] = lo;
    }
}

// ---------------------------------------------------------------------------
// RoPE + split: read fp32, rotate, write bf16 hi/lo
// ---------------------------------------------------------------------------
__global__ void rope_split(const float* __restrict__ src,
                           bf16* __restrict__ oh, bf16* __restrict__ ol,
                           int heads, int total)
{
    int i = blockIdx.x * blockDim.x + threadIdx.x;
    if (i >= total) return;
    int d   = i & 63;
    int hh  = (i >> 6) % heads;
    int row = i / (heads * 64);
    int t   = row & (T_ - 1);

    float inv = powf(10000.0f, -(float)d * (1.0f / 64.0f));
    float ang = (float)t * inv;
    float s = sinf(ang), c = cosf(ang);

    size_t p = (size_t)row * (heads * DH_) + hh * DH_ + d;
    float x1 = src[p], x2 = src[p + 64];
    float y1 = x1 * c - x2 * s;
    float y2 = x1 * s + x2 * c;
    bf16 h1, l1, h2, l2;
    split_bf16(y1, h1, l1);
    split_bf16(y2, h2, l2);
    oh[p] = h1;      ol[p] = l1;
    oh[p + 64] = h2; ol[p + 64] = l2;
}

// ---------------------------------------------------------------------------
// Single-pass causal softmax: read fp32 scores row, write bf16 hi/lo probs.
// ---------------------------------------------------------------------------
__global__ void __launch_bounds__(128) softmax_split(
    const float* __restrict__ S, bf16* __restrict__ PH, bf16* __restrict__ PL)
{
    int r = blockIdx.x;
    int z = r >> 10;
    int t = r & (T_ - 1);
    const float* row = S + (size_t)z * T_ * T_ + (size_t)t * T_;
    int tid = threadIdx.x;

    __shared__ float red[4];

    float v[8];
    float m = -INFINITY;
    #pragma unroll
    for (int i = 0; i < 8; i++) {
        int j = tid + 128 * i;
        v[i] = (j <= t) ? row[j] : -INFINITY;
        m = fmaxf(m, v[i]);
    }
    #pragma unroll
    for (int o = 16; o > 0; o >>= 1) m = fmaxf(m, __shfl_xor_sync(0xFFFFFFFFu, m, o));
    if ((tid & 31) == 0) red[tid >> 5] = m;
    __syncthreads();
    m = fmaxf(fmaxf(red[0], red[1]), fmaxf(red[2], red[3]));
    __syncthreads();

    float ssum = 0.0f;
    #pragma unroll
    for (int i = 0; i < 8; i++) {
        int j = tid + 128 * i;
        float e = (j <= t) ? __expf(v[i] - m) : 0.0f;
        v[i] = e;
        ssum += e;
    }
    #pragma unroll
    for (int o = 16; o > 0; o >>= 1) ssum += __shfl_xor_sync(0xFFFFFFFFu, ssum, o);
    if ((tid & 31) == 0) red[tid >> 5] = ssum;
    __syncthreads();
    ssum = red[0] + red[1] + red[2] + red[3];
    float inv = 1.0f / ssum;

    size_t base = (size_t)z * T_ * T_ + (size_t)t * T_;
    #pragma unroll
    for (int i = 0; i < 8; i++) {
        int j = tid + 128 * i;
        bf16 hi, lo; split_bf16(v[i] * inv, hi, lo);
        PH[base + j] = hi;
        PL[base + j] = lo;
    }
}

// ---------------------------------------------------------------------------
// HMMA bf16x3 GEMM. CTA 128x128, 8 warps (2x4), warp 64x32, K-chunk 64,
// double-buffered cp.async, mma.sync m16n8k16 .row.col, fp32 accum.
// TCMODE 0: QKV routing. TCMODE 2: plain (+residual).
// TCMODE 3: scores  S[z] = (Q K^T)/sqrt(DH), causal tile skip.
// TCMODE 4: PV      Y[z] = P V  (A=probs, B=V^T), causal K truncation,
//                   output written as bf16 hi/lo split.
// ---------------------------------------------------------------------------
#define KC      64
#define TILE_B  (128 * 72 * 2)         // 18432 B per tile (144 B row stride)
#define BUF_B   (4 * TILE_B)
#define TC_SMEM_BYTES (2 * BUF_B)      // 147456 B

template <int TCMODE>
__global__ void __launch_bounds__(256) tc_gemm(
    const bf16* __restrict__ Ah, const bf16* __restrict__ Al,
    const bf16* __restrict__ Bh, const bf16* __restrict__ Bl,
    float* __restrict__ C0, float* __restrict__ C1, float* __restrict__ C2c,
    const float* __restrict__ R,
    bf16* __restrict__ YH, bf16* __restrict__ YL, int K)
{
    extern __shared__ char smem[];
    unsigned sbase = smem_u32(smem);

    int m0  = blockIdx.y * 128;
    int n0g = blockIdx.x * 128;
    int z   = blockIdx.z;

    int lda = K, ldb = K, Keff = K;
    size_t aoff = 0, boff = 0;
    int zb = 0, zh = 0;

    if (TCMODE == 3) {
        if (n0g > m0 + 127) return;                   // fully-masked tile
        zb = z >> 4; zh = z & 15;
        int kvh = zh >> 2;
        aoff = (size_t)zb * T_ * DIM_ + zh * DH_;  lda = DIM_;
        boff = (size_t)zb * T_ * (HKV_*DH_) + kvh * DH_; ldb = HKV_*DH_;
        Keff = DH_;                                   // 128
    } else if (TCMODE == 4) {
        zb = z >> 4; zh = z & 15;
        int kvh = zh >> 2;
        aoff = (size_t)z * T_ * T_;                 lda = T_;
        boff = (size_t)(zb * HKV_ + kvh) * DH_ * T_; ldb = T_;
        Keff = m0 + 128;                              // causal truncation
    }

    float* Cp = C0; int ldc = 0; int n0 = n0g;
    if (TCMODE == 0) {
        if (n0g < 2048)      { Cp = C0;  ldc = DIM_; n0 = n0g; }
        else if (n0g < 2560) { Cp = C1;  ldc = 512;  n0 = n0g - 2048; }
        else                 { Cp = C2c; ldc = 512;  n0 = n0g - 2560; }
    } else if (TCMODE == 2) {
        Cp = C0; ldc = gridDim.x * 128; n0 = n0g;
    } else if (TCMODE == 3) {
        Cp = C0 + (size_t)z * T_ * T_; ldc = T_; n0 = n0g;
    }

    int tid  = threadIdx.x;
    int wid  = tid >> 5;
    int lane = tid & 31;
    int warp_m = (wid >> 2) * 64;
    int warp_n = (wid & 3) * 32;

    const bf16* pAh = Ah + aoff;
    const bf16* pAl = Al + aoff;
    const bf16* pBh = Bh + boff;
    const bf16* pBl = Bl + boff;

    float acc[4][4][4];
    #pragma unroll
    for (int i = 0; i < 4; i++)
        #pragma unroll
        for (int j = 0; j < 4; j++)
            #pragma unroll
            for (int e = 0; e < 4; e++) acc[i][j][e] = 0.0f;

    const int nch = Keff / KC;

    // ---- prefetch chunk 0 into buffer 0 ----
    {
        const bf16* srcs[4] = { pAh, pAl, pBh, pBl };
        #pragma unroll
        for (int t4 = 0; t4 < 4; t4++) {
            unsigned tb = t4 * TILE_B;
            int rbase = (t4 < 2) ? m0 : n0g;
            int ld    = (t4 < 2) ? lda : ldb;
            #pragma unroll
            for (int i = 0; i < 4; i++) {
                int u = tid + 256 * i;
                int row = u >> 3, col = u & 7;
                cp16(sbase + tb + row * 144 + col * 16,
                     srcs[t4] + (size_t)(rbase + row) * ld + col * 8);
            }
        }
        cp_commit();
        cp_wait0();
    }
    __syncthreads();

    int cur = 0;
    for (int c = 0; c < nch; c++) {
        bool has_next = (c + 1) < nch;
        if (has_next) {
            int nxt = cur ^ 1;
            const bf16* srcs[4] = { pAh, pAl, pBh, pBl };
            int c0 = (c + 1) * KC;
            #pragma unroll
            for (int t4 = 0; t4 < 4; t4++) {
                unsigned tb = nxt * BUF_B + t4 * TILE_B;
                int rbase = (t4 < 2) ? m0 : n0g;
                int ld    = (t4 < 2) ? lda : ldb;
                #pragma unroll
                for (int i = 0; i < 4; i++) {
                    int u = tid + 256 * i;
                    int row = u >> 3, col = u & 7;
                    cp16(sbase + tb + row * 144 + col * 16,
                         srcs[t4] + (size_t)(rbase + row) * ld + c0 + col * 8);
                }
            }
            cp_commit();
        }

        unsigned AHb = sbase + cur * BUF_B;
        unsigned ALb = AHb + TILE_B;
        const char* BHp = smem + cur * BUF_B + 2 * TILE_B;
        const char* BLp = smem + cur * BUF_B + 3 * TILE_B;

        int lr  = lane & 15, lc8 = lane >> 4;
        int gid = lane >> 2, tig = lane & 3;

        #pragma unroll
        for (int k16 = 0; k16 < KC; k16 += 16) {
            unsigned ah[4][4], al[4][4];
            #pragma unroll
            for (int mi = 0; mi < 4; mi++) {
                unsigned off = (unsigned)((warp_m + mi*16 + lr) * 144 + (k16 + lc8*8) * 2);
                ldsm4(ah[mi], AHb + off);
                ldsm4(al[mi], ALb + off);
            }
            unsigned bh[4][2], bl[4][2];
            #pragma unroll
            for (int ni = 0; ni < 4; ni++) {
                unsigned off = (unsigned)((warp_n + ni*8 + gid) * 144 + (k16 + tig*2) * 2);
                bh[ni][0] = *(const unsigned*)(BHp + off);
                bh[ni][1] = *(const unsigned*)(BHp + off + 16);
                bl[ni][0] = *(const unsigned*)(BLp + off);
                bl[ni][1] = *(const unsigned*)(BLp + off + 16);
            }
            #pragma unroll
            for (int mi = 0; mi < 4; mi++)
                #pragma unroll
                for (int ni = 0; ni < 4; ni++) {
                    mma16816(acc[mi][ni], ah[mi], bh[ni]);
                    mma16816(acc[mi][ni], ah[mi], bl[ni]);
                    mma16816(acc[mi][ni], al[mi], bh[ni]);
                }
        }

        if (has_next) {
            cp_wait0();
            __syncthreads();
            cur ^= 1;
        }
    }

    // ---- epilogue ----
    {
        int gid = lane >> 2, tig = lane & 3;
        #pragma unroll
        for (int mi = 0; mi < 4; mi++) {
            #pragma unroll
            for (int ni = 0; ni < 4; ni++) {
                int m  = m0 + warp_m + mi*16 + gid;
                int nn = n0 + warp_n + ni*8 + tig*2;
                float* c = acc[mi][ni];
                if (TCMODE == 4) {
                    size_t o0 = (size_t)(zb * T_ + m)     * DIM_ + zh * DH_ + nn;
                    size_t o1 = (size_t)(zb * T_ + m + 8) * DIM_ + zh * DH_ + nn;
                    bf16 h0a, l0a, h0b, l0b, h1a, l1a, h1b, l1b;
                    split_bf16(c[0], h0a, l0a); split_bf16(c[1], h0b, l0b);
                    split_bf16(c[2], h1a, l1a); split_bf16(c[3], h1b, l1b);
                    __nv_bfloat162 ph0; ph0.x = h0a; ph0.y = h0b;
                    __nv_bfloat162 pl0; pl0.x = l0a; pl0.y = l0b;
                    __nv_bfloat162 ph1; ph1.x = h1a; ph1.y = h1b;
                    __nv_bfloat162 pl1; pl1.x = l1a; pl1.y = l1b;
                    *(__nv_bfloat162*)&YH[o0] = ph0;
                    *(__nv_bfloat162*)&YL[o0] = pl0;
                    *(__nv_bfloat162*)&YH[o1] = ph1;
                    *(__nv_bfloat162*)&YL[o1] = pl1;
                } else if (TCMODE == 3) {
                    const float sc = 0.08838834764831845f;   // 1/sqrt(128)
                    float* p0 = Cp + (size_t)m * ldc + nn;
                    float* p1 = Cp + (size_t)(m + 8) * ldc + nn;
                    *(float2*)p0 = make_float2(c[0] * sc, c[1] * sc);
                    *(float2*)p1 = make_float2(c[2] * sc, c[3] * sc);
                } else {
                    float* p0 = Cp + (size_t)m * ldc + nn;
                    float* p1 = Cp + (size_t)(m + 8) * ldc + nn;
                    if (TCMODE == 2 && R != nullptr) {
                        float2 rv0 = *(const float2*)(R + (size_t)m * ldc + nn);
                        float2 rv1 = *(const float2*)(R + (size_t)(m + 8) * ldc + nn);
                        *(float2*)p0 = make_float2(c[0] + rv0.x, c[1] + rv0.y);
                        *(float2*)p1 = make_float2(c[2] + rv1.x, c[3] + rv1.y);
                    } else {
                        *(float2*)p0 = make_float2(c[0], c[1]);
                        *(float2*)p1 = make_float2(c[2], c[3]);
                    }
                }
            }
        }
    }
}

// ---------------------------------------------------------------------------
// Fused FFN12 GEMM: per CTA, two K-loops over the same A row-block:
//   phase 0: c1 = A @ W1[n-block],  phase 1: c2 = A @ W2[n-block]
// Epilogue: out = silu(c1) * c2, written as bf16 hi/lo split (no fp32 h1/h2).
// ---------------------------------------------------------------------------
__global__ void __launch_bounds__(256) ffn12_gemm(
    const bf16* __restrict__ Ah, const bf16* __restrict__ Al,
    const bf16* __restrict__ W1h, const bf16* __restrict__ W1l,
    const bf16* __restrict__ W2h, const bf16* __restrict__ W2l,
    bf16* __restrict__ OH, bf16* __restrict__ OL)
{
    extern __shared__ char smem[];
    unsigned sbase = smem_u32(smem);

    int m0 = blockIdx.y * 128;
    int n0 = blockIdx.x * 128;

    int tid  = threadIdx.x;
    int wid  = tid >> 5;
    int lane = tid & 31;
    int warp_m = (wid >> 2) * 64;
    int warp_n = (wid & 3) * 32;

    float acc[2][4][4][4];
    #pragma unroll
    for (int p = 0; p < 2; p++)
        #pragma unroll
        for (int i = 0; i < 4; i++)
            #pragma unroll
            for (int j = 0; j < 4; j++)
                #pragma unroll
                for (int e = 0; e < 4; e++) acc[p][i][j][e] = 0.0f;

    const int nch = DIM_ / KC;    // 32

    #pragma unroll 1
    for (int phase = 0; phase < 2; phase++) {
        const bf16* pBh = (phase == 0) ? W1h : W2h;
        const bf16* pBl = (phase == 0) ? W1l : W2l;
        float (*ac)[4][4] = acc[phase];

        // prefetch chunk 0 into buffer 0
        {
            const bf16* srcs[4] = { Ah, Al, pBh, pBl };
            #pragma unroll
            for (int t4 = 0; t4 < 4; t4++) {
                unsigned tb = t4 * TILE_B;
                int rbase = (t4 < 2) ? m0 : n0;
                #pragma unroll
                for (int i = 0; i < 4; i++) {
                    int u = tid + 256 * i;
                    int row = u >> 3, col = u & 7;
                    cp16(sbase + tb + row * 144 + col * 16,
                         srcs[t4] + (size_t)(rbase + row) * DIM_ + col * 8);
                }
            }
            cp_commit();
            cp_wait0();
        }
        __syncthreads();

        int cur = 0;
        for (int c = 0; c < nch; c++) {
            bool has_next = (c + 1) < nch;
            if (has_next) {
                int nxt = cur ^ 1;
                const bf16* srcs[4] = { Ah, Al, pBh, pBl };
                int c0 = (c + 1) * KC;
                #pragma unroll
                for (int t4 = 0; t4 < 4; t4++) {
                    unsigned tb = nxt * BUF_B + t4 * TILE_B;
                    int rbase = (t4 < 2) ? m0 : n0;
                    #pragma unroll
                    for (int i = 0; i < 4; i++) {
                        int u = tid + 256 * i;
                        int row = u >> 3, col = u & 7;
                        cp16(sbase + tb + row * 144 + col * 16,
                             srcs[t4] + (size_t)(rbase + row) * DIM_ + c0 + col * 8);
                    }
                }
                cp_commit();
            }

            unsigned AHb = sbase + cur * BUF_B;
            unsigned ALb = AHb + TILE_B;
            const char* BHp = smem + cur * BUF_B + 2 * TILE_B;
            const char* BLp = smem + cur * BUF_B + 3 * TILE_B;

            int lr  = lane & 15, lc8 = lane >> 4;
            int gid = lane >> 2, tig = lane & 3;

            #pragma unroll
            for (int k16 = 0; k16 < KC; k16 += 16) {
                unsigned ah[4][4], al[4][4];
                #pragma unroll
                for (int mi = 0; mi < 4; mi++) {
                    unsigned off = (unsigned)((warp_m + mi*16 + lr) * 144 + (k16 + lc8*8) * 2);
                    ldsm4(ah[mi], AHb + off);
                    ldsm4(al[mi], ALb + off);
                }
                unsigned bh[4][2], bl[4][2];
                #pragma unroll
                for (int ni = 0; ni < 4; ni++) {
                    unsigned off = (unsigned)((warp_n + ni*8 + gid) * 144 + (k16 + tig*2) * 2);
                    bh[ni][0] = *(const unsigned*)(BHp + off);
                    bh[ni][1] = *(const unsigned*)(BHp + off + 16);
                    bl[ni][0] = *(const unsigned*)(BLp + off);
                    bl[ni][1] = *(const unsigned*)(BLp + off + 16);
                }
                #pragma unroll
                for (int mi = 0; mi < 4; mi++)
                    #pragma unroll
                    for (int ni = 0; ni < 4; ni++) {
                        mma16816(ac[mi][ni], ah[mi], bh[ni]);
                        mma16816(ac[mi][ni], ah[mi], bl[ni]);
                        mma16816(ac[mi][ni], al[mi], bh[ni]);
                    }
            }

            if (has_next) {
                cp_wait0();
                __syncthreads();
                cur ^= 1;
            }
        }
        __syncthreads();   // buffers must be fully consumed before next phase
    }

    // ---- epilogue: silu(c1) * c2, bf16 split ----
    {
        int gid = lane >> 2, tig = lane & 3;
        #pragma unroll
        for (int mi = 0; mi < 4; mi++) {
            #pragma unroll
            for (int ni = 0; ni < 4; ni++) {
                int m  = m0 + warp_m + mi*16 + gid;
                int nn = n0 + warp_n + ni*8 + tig*2;
                float* c1 = acc[0][mi][ni];
                float* c2 = acc[1][mi][ni];
                float r[4];
                #pragma unroll
                for (int e = 0; e < 4; e++)
                    r[e] = c1[e] / (1.0f + __expf(-c1[e])) * c2[e];

                size_t o0 = (size_t)m * HID_ + nn;
                size_t o1 = (size_t)(m + 8) * HID_ + nn;
                bf16 h0a, l0a, h0b, l0b, h1a, l1a, h1b, l1b;
                split_bf16(r[0], h0a, l0a); split_bf16(r[1], h0b, l0b);
                split_bf16(r[2], h1a, l1a); split_bf16(r[3], h1b, l1b);
                __nv_bfloat162 ph0; ph0.x = h0a; ph0.y = h0b;
                __nv_bfloat162 pl0; pl0.x = l0a; pl0.y = l0b;
                __nv_bfloat162 ph1; ph1.x = h1a; ph1.y = h1b;
                __nv_bfloat162 pl1; pl1.x = l1a; pl1.y = l1b;
                *(__nv_bfloat162*)&OH[o0] = ph0;
                *(__nv_bfloat162*)&OL[o0] = pl0;
                *(__nv_bfloat162*)&OH[o1] = ph1;
                *(__nv_bfloat162*)&OL[o1] = pl1;
            }
        }
    }
}

// ---------------------------------------------------------------------------
// Launch
// ---------------------------------------------------------------------------
extern "C" void kernel_launch(void* const* d_in, const int* in_sizes, int n_in,
                              void* d_out, int out_size)
{
    const float* x      = (const float*)d_in[0];
    const float* attn_w = (const float*)d_in[1];
    const float* ff_w   = (const float*)d_in[2];
    const float* wq     = (const float*)d_in[3];
    const float* wk     = (const float*)d_in[4];
    const float* wv     = (const float*)d_in[5];
    const float* wo     = (const float*)d_in[6];
    const float* w1     = (const float*)d_in[7];
    const float* w2     = (const float*)d_in[8];
    const float* w3     = (const float*)d_in[9];
    float* out = (float*)d_out;

    float *q, *k, *v, *s;
    bf16 *ah, *al, *qh, *ql, *kh, *kl, *vth, *vtl, *ph, *pl, *yh, *yl, *hh, *hl;
    bf16 *wqkvh, *wqkvl, *woh, *wol, *w12h, *w12l, *w3h, *w3l;
    cudaGetSymbolAddress((void**)&q,   g_q);
    cudaGetSymbolAddress((void**)&k,   g_k);
    cudaGetSymbolAddress((void**)&v,   g_v);
    cudaGetSymbolAddress((void**)&s,   g_s);
    cudaGetSymbolAddress((void**)&ah,  g_ah);
    cudaGetSymbolAddress((void**)&al,  g_al);
    cudaGetSymbolAddress((void**)&qh,  g_qh);
    cudaGetSymbolAddress((void**)&ql,  g_ql);
    cudaGetSymbolAddress((void**)&kh,  g_kh);
    cudaGetSymbolAddress((void**)&kl,  g_kl);
    cudaGetSymbolAddress((void**)&vth, g_vth);
    cudaGetSymbolAddress((void**)&vtl, g_vtl);
    cudaGetSymbolAddress((void**)&ph,  g_ph);
    cudaGetSymbolAddress((void**)&pl,  g_pl);
    cudaGetSymbolAddress((void**)&yh,  g_yh);
    cudaGetSymbolAddress((void**)&yl,  g_yl);
    cudaGetSymbolAddress((void**)&hh,  g_hh);
    cudaGetSymbolAddress((void**)&hl,  g_hl);
    cudaGetSymbolAddress((void**)&wqkvh, g_wqkv_h);
    cudaGetSymbolAddress((void**)&wqkvl, g_wqkv_l);
    cudaGetSymbolAddress((void**)&woh,   g_wo_h);
    cudaGetSymbolAddress((void**)&wol,   g_wo_l);
    cudaGetSymbolAddress((void**)&w12h,  g_w12_h);
    cudaGetSymbolAddress((void**)&w12l,  g_w12_l);
    cudaGetSymbolAddress((void**)&w3h,   g_w3_h);
    cudaGetSymbolAddress((void**)&w3l,   g_w3_l);

    cudaFuncSetAttribute(tc_gemm<0>, cudaFuncAttributeMaxDynamicSharedMemorySize, TC_SMEM_BYTES);
    cudaFuncSetAttribute(tc_gemm<2>, cudaFuncAttributeMaxDynamicSharedMemorySize, TC_SMEM_BYTES);
    cudaFuncSetAttribute(tc_gemm<3>, cudaFuncAttributeMaxDynamicSharedMemorySize, TC_SMEM_BYTES);
    cudaFuncSetAttribute(tc_gemm<4>, cudaFuncAttributeMaxDynamicSharedMemorySize, TC_SMEM_BYTES);
    cudaFuncSetAttribute(ffn12_gemm, cudaFuncAttributeMaxDynamicSharedMemorySize, TC_SMEM_BYTES);

    dim3 tb(32, 8);

    wsplit_t<<<dim3(DIM_/32, DIM_/32), tb>>>(wq, wqkvh, wqkvl, DIM_, DIM_, 0);
    wsplit_t<<<dim3(512/32,  DIM_/32), tb>>>(wk, wqkvh, wqkvl, DIM_, 512,  2048);
    wsplit_t<<<dim3(512/32,  DIM_/32), tb>>>(wv, wqkvh, wqkvl, DIM_, 512,  2560);
    rmsnorm_split<<<M_TOK, 256>>>(x, attn_w, ah, al);
    wsplit_t<<<dim3(HID_/32, DIM_/32), tb>>>(w1, w12h, w12l, DIM_, HID_, 0);

    // QKV (N = 3072)
    tc_gemm<0><<<dim3(3072/128, M_TOK/128), 256, TC_SMEM_BYTES>>>(
        ah, al, wqkvh, wqkvl, q, k, v, nullptr, nullptr, nullptr, DIM_);

    wsplit_t<<<dim3(HID_/32, DIM_/32), tb>>>(w2, w12h, w12l, DIM_, HID_, HID_);
    wsplit_t<<<dim3(DIM_/32, DIM_/32), tb>>>(wo, woh, wol, DIM_, DIM_, 0);
    wsplit_t<<<dim3(DIM_/32, HID_/32), tb>>>(w3, w3h, w3l, HID_, DIM_, 0);

    {
        int tq = M_TOK * H_ * 64;
        rope_split<<<(tq + 255) / 256, 256>>>(q, qh, ql, H_, tq);
        int tk = M_TOK * HKV_ * 64;
        rope_split<<<(tk + 255) / 256, 256>>>(k, kh, kl, HKV_, tk);
    }
    vsplit_t<<<dim3(DH_/32, T_/32, B_*HKV_), tb>>>(v, vth, vtl);

    // scores: S[z] = (Q K^T)/sqrt(DH), causal tiles skipped
    tc_gemm<3><<<dim3(T_/128, T_/128, B_*H_), 256, TC_SMEM_BYTES>>>(
        qh, ql, kh, kl, s, nullptr, nullptr, nullptr, nullptr, nullptr, DH_);

    softmax_split<<<B_*H_*T_, 128>>>(s, ph, pl);

    // PV: y = P V, output bf16 split
    tc_gemm<4><<<dim3(1, T_/128, B_*H_), 256, TC_SMEM_BYTES>>>(
        ph, pl, vth, vtl, nullptr, nullptr, nullptr, nullptr, yh, yl, T_);

    // out = x + y @ wo
    tc_gemm<2><<<dim3(DIM_/128, M_TOK/128), 256, TC_SMEM_BYTES>>>(
        yh, yl, woh, wol, out, nullptr, nullptr, x, nullptr, nullptr, DIM_);

    rmsnorm_split<<<M_TOK, 256>>>(out, ff_w, ah, al);

    // fused FFN12: h = silu(A W1) * (A W2), written directly as bf16 split
    ffn12_gemm<<<dim3(HID_/128, M_TOK/128), 256, TC_SMEM_BYTES>>>(
        ah, al, w12h, w12l, w12h + (size_t)HID_ * DIM_, w12l + (size_t)HID_ * DIM_,
        hh, hl);

    // out = out + h @ w3
    tc_gemm<2><<<dim3(DIM_/128, M_TOK/128), 256, TC_SMEM_BYTES>>>(
        hh, hl, w3h, w3l, out, nullptr, nullptr, out, nullptr, nullptr, HID_);
}